// round 15
// baseline (speedup 1.0000x reference)
#include <cuda_runtime.h>
#include <cuda_fp16.h>
#include <cstdint>

#define B_ROWS 16384
#define IN_DIM 64
#define OUT_DIM 4096
#define BM 128
#define BN 256

// ---- device-global scratch (alloc-guard-safe) ----
__device__ __half g_xh[B_ROWS * IN_DIM];
__device__ __half g_ch[OUT_DIM * IN_DIM];
__device__ float g_xn[B_ROWS];
__device__ float g_cn[OUT_DIM];
__device__ float g_iv[OUT_DIM];

// ---- smem layout (bytes) ----
#define SA      0            // 16KB (128 rows x 128B)
#define SB      16384        // 32KB (256 rows x 128B)
#define S_XN    49152        // 512B
#define S_CN    49664        // 1KB (256 f32)
#define S_IV    50688        // 1KB
#define S_STAGE 51712        // 8 warps x 2KB
#define SMEM_TOTAL 68096

__device__ __forceinline__ uint32_t s2u(const void* p) {
    uint32_t a;
    asm("{ .reg .u64 t; cvta.to.shared.u64 t, %1; cvt.u32.u64 %0, t; }" : "=r"(a) : "l"(p));
    return a;
}
__device__ __forceinline__ void cp16(uint32_t dst, const void* src) {
    asm volatile("cp.async.cg.shared.global [%0], [%1], 16;" :: "r"(dst), "l"(src));
}
__device__ __forceinline__ void ldm_x4(uint32_t* r, uint32_t addr) {
    asm volatile("ldmatrix.sync.aligned.m8n8.x4.shared.b16 {%0,%1,%2,%3}, [%4];"
                 : "=r"(r[0]), "=r"(r[1]), "=r"(r[2]), "=r"(r[3]) : "r"(addr));
}
__device__ __forceinline__ void stm_x4(uint32_t addr, uint32_t r0, uint32_t r1,
                                       uint32_t r2, uint32_t r3) {
    asm volatile("stmatrix.sync.aligned.m8n8.x4.shared.b16 [%0], {%1,%2,%3,%4};"
                 :: "r"(addr), "r"(r0), "r"(r1), "r"(r2), "r"(r3) : "memory");
}
__device__ __forceinline__ void mma_h(uint32_t* c, const uint32_t* a,
                                      uint32_t b0, uint32_t b1) {
    asm volatile(
        "mma.sync.aligned.m16n8k16.row.col.f16.f16.f16.f16 "
        "{%0,%1}, {%2,%3,%4,%5}, {%6,%7}, {%0,%1};"
        : "+r"(c[0]), "+r"(c[1])
        : "r"(a[0]), "r"(a[1]), "r"(a[2]), "r"(a[3]), "r"(b0), "r"(b1));
}
__device__ __forceinline__ float ex2a(float x) {
    float r;
    asm("ex2.approx.f32 %0, %1;" : "=f"(r) : "f"(x));
    return r;
}

// ---- prep (fused): f32 -> fp16, row norms, inv_sigma2 ----
__global__ void prep_all(const float* __restrict__ x, const float* __restrict__ c,
                         const float* __restrict__ ls) {
    int gw = (blockIdx.x * blockDim.x + threadIdx.x) >> 5;
    int lane = threadIdx.x & 31;
    const float* src;
    __half2* dst;
    int row;
    if (gw < B_ROWS) {
        row = gw; src = x; dst = (__half2*)g_xh;
    } else {
        row = gw - B_ROWS;
        if (row >= OUT_DIM) return;
        src = c; dst = (__half2*)g_ch;
    }
    float2 v = ((const float2*)src)[row * 32 + lane];
    dst[row * 32 + lane] = __floats2half2_rn(v.x, v.y);
    float s = v.x * v.x + v.y * v.y;
#pragma unroll
    for (int o = 16; o; o >>= 1) s += __shfl_xor_sync(0xffffffffu, s, o);
    if (lane == 0) {
        if (gw < B_ROWS) g_xn[row] = s;
        else { g_cn[row] = s; g_iv[row] = __expf(-2.0f * ls[row]); }
    }
}

// ---- main: 128x256 tile, 64x64 warp tiles, f16-acc mma, 2-FMA epilogue ----
__global__ void __launch_bounds__(256, 2)
rbf_mma(float* __restrict__ out) {
    extern __shared__ char smem[];
    const uint32_t sb = s2u(smem);
    const int tid = threadIdx.x;
    const int bn = blockIdx.x * BN;
    const int bm = blockIdx.y * BM;

    // ---- global -> smem via cp.async, XOR-swizzled (q -> q ^ (row&7)) ----
    {
        const __half* ax = g_xh + (size_t)bm * IN_DIM;
        const __half* bc = g_ch + (size_t)bn * IN_DIM;
#pragma unroll
        for (int i = 0; i < 4; i++) {
            int l = tid + i * 256;
            int row = l >> 3, q = l & 7;
            cp16(sb + SA + row * 128 + ((q ^ (row & 7)) << 4), ax + l * 8);
        }
#pragma unroll
        for (int i = 0; i < 8; i++) {
            int l = tid + i * 256;
            int row = l >> 3, q = l & 7;
            cp16(sb + SB + row * 128 + ((q ^ (row & 7)) << 4), bc + l * 8);
        }
        if (tid < 32)       cp16(sb + S_XN + tid * 16, g_xn + bm + tid * 4);
        else if (tid < 96)  cp16(sb + S_CN + (tid - 32) * 16, g_cn + bn + (tid - 32) * 4);
        else if (tid < 160) cp16(sb + S_IV + (tid - 96) * 16, g_iv + bn + (tid - 96) * 4);
        asm volatile("cp.async.commit_group;" ::: "memory");
        asm volatile("cp.async.wait_group 0;" ::: "memory");
    }
    __syncthreads();

    const int wid = tid >> 5, lane = tid & 31;
    const int wm = wid >> 2, wn = wid & 3;   // 2x4 warp grid, 64x64 warp tiles
    const int lrow = lane & 15;
    const int ksel = lane >> 4;
    const int szk = lrow & 7;

    uint32_t aBase[4], bBase[4];
#pragma unroll
    for (int t = 0; t < 4; t++) {
        aBase[t] = sb + SA + (wm * 64 + t * 16 + lrow) * 128;
        bBase[t] = sb + SB + (wn * 64 + t * 16 + lrow) * 128;
    }

    uint32_t acc[4][8][2];                   // f16x2-packed accumulators
#pragma unroll
    for (int i = 0; i < 4; i++)
#pragma unroll
        for (int j = 0; j < 8; j++) { acc[i][j][0] = 0u; acc[i][j][1] = 0u; }

#pragma unroll
    for (int ks = 0; ks < 4; ks++) {
        const int kc = ks * 2 + ksel;
        const uint32_t ko = (uint32_t)((kc ^ szk) << 4);
        uint32_t Ah[4][4], Bh[4][4];
#pragma unroll
        for (int t = 0; t < 4; t++) ldm_x4(Ah[t], aBase[t] + ko);
#pragma unroll
        for (int t = 0; t < 4; t++) ldm_x4(Bh[t], bBase[t] + ko);
#pragma unroll
        for (int mt = 0; mt < 4; mt++)
#pragma unroll
            for (int p = 0; p < 4; p++) {
                mma_h(acc[mt][p * 2 + 0], Ah[mt], Bh[p][0], Bh[p][2]);
                mma_h(acc[mt][p * 2 + 1], Ah[mt], Bh[p][1], Bh[p][3]);
            }
    }

    // ---- epilogue: swizzled stage; arg = fma(d, s_j, fma(-xn, ivl_j, nci_j)) ----
    const float* xn_s = (const float*)(smem + S_XN);
    const float* cn_s = (const float*)(smem + S_CN);
    const float* iv_s = (const float*)(smem + S_IV);
    const float L2E = 1.4426950408889634f;

    const int prow = lane >> 3;          // 0..3
    const int pcol = lane & 7;           // matrix index / col-chunk
    float s8[8], ivl8[8], nci8[8];
#pragma unroll
    for (int j = 0; j < 8; j++) {
        int col = wn * 64 + pcol * 8 + j;
        float ivl = iv_s[col] * L2E;
        ivl8[j] = ivl;
        s8[j] = 2.0f * ivl;
        nci8[j] = -cn_s[col] * ivl;
    }

    const uint32_t wstage = sb + S_STAGE + wid * 2048;
    const int m_loc = lane >> 3;
    const int rr_s = lane & 7;

#pragma unroll
    for (int mt = 0; mt < 4; mt++) {
#pragma unroll
        for (int g = 0; g < 2; g++)
#pragma unroll
            for (int qb = 0; qb < 8; qb += 4) {
                int m = qb + m_loc;
                uint32_t a = wstage + (uint32_t)((g * 8 + m) * 128 +
                             (((rr_s + m) & 7) << 4));
                stm_x4(a, acc[mt][qb + 0][g], acc[mt][qb + 1][g],
                          acc[mt][qb + 2][g], acc[mt][qb + 3][g]);
            }
        __syncwarp();

#pragma unroll
        for (int k = 0; k < 4; k++) {
            int r = k * 4 + prow;            // 0..15
            int g = r >> 3, rr = r & 7;
            uint32_t a = wstage + (uint32_t)((g * 8 + pcol) * 128 +
                         (((rr + pcol) & 7) << 4));
            uint4 raw = *(const uint4*)(smem + (a - sb));
            float2 f0 = __half22float2(*reinterpret_cast<__half2*>(&raw.x));
            float2 f1 = __half22float2(*reinterpret_cast<__half2*>(&raw.y));
            float2 f2 = __half22float2(*reinterpret_cast<__half2*>(&raw.z));
            float2 f3 = __half22float2(*reinterpret_cast<__half2*>(&raw.w));
            int row = wm * 64 + mt * 16 + r;
            float nxn = -xn_s[row];
            float t0 = fmaf(nxn, ivl8[0], nci8[0]);
            float t1 = fmaf(nxn, ivl8[1], nci8[1]);
            float t2 = fmaf(nxn, ivl8[2], nci8[2]);
            float t3 = fmaf(nxn, ivl8[3], nci8[3]);
            float t4 = fmaf(nxn, ivl8[4], nci8[4]);
            float t5 = fmaf(nxn, ivl8[5], nci8[5]);
            float t6 = fmaf(nxn, ivl8[6], nci8[6]);
            float t7 = fmaf(nxn, ivl8[7], nci8[7]);
            float4 o0, o1;
            o0.x = ex2a(fmaf(f0.x, s8[0], t0));
            o0.y = ex2a(fmaf(f0.y, s8[1], t1));
            o0.z = ex2a(fmaf(f1.x, s8[2], t2));
            o0.w = ex2a(fmaf(f1.y, s8[3], t3));
            o1.x = ex2a(fmaf(f2.x, s8[4], t4));
            o1.y = ex2a(fmaf(f2.y, s8[5], t5));
            o1.z = ex2a(fmaf(f3.x, s8[6], t6));
            o1.w = ex2a(fmaf(f3.y, s8[7], t7));
            float* op = out + (size_t)(bm + row) * OUT_DIM + bn + wn * 64 + pcol * 8;
            *(float4*)(op) = o0;
            *(float4*)(op + 4) = o1;
        }
        __syncwarp();
    }
}

extern "C" void kernel_launch(void* const* d_in, const int* in_sizes, int n_in,
                              void* d_out, int out_size) {
    const float* x  = (const float*)d_in[0];
    const float* c  = (const float*)d_in[1];
    const float* ls = (const float*)d_in[2];
    float* out = (float*)d_out;
    (void)in_sizes; (void)n_in; (void)out_size;

    cudaFuncSetAttribute(rbf_mma, cudaFuncAttributeMaxDynamicSharedMemorySize, SMEM_TOTAL);

    prep_all<<<(B_ROWS + OUT_DIM) / 8, 256>>>(x, c, ls);

    dim3 grid(OUT_DIM / BN, B_ROWS / BM);
    rbf_mma<<<grid, 256, SMEM_TOTAL>>>(out);
}

// round 16
// speedup vs baseline: 1.2224x; 1.2224x over previous
#include <cuda_runtime.h>
#include <cuda_fp16.h>
#include <cstdint>

#define B_ROWS 16384
#define IN_DIM 64
#define OUT_DIM 4096
#define BM 128
#define BN 128

// ---- device-global scratch (alloc-guard-safe) ----
__device__ __half g_xh[B_ROWS * IN_DIM];
__device__ __half g_ch[OUT_DIM * IN_DIM];
__device__ float g_xn[B_ROWS];
__device__ float g_cn[OUT_DIM];
__device__ float g_iv[OUT_DIM];

// ---- smem layout (bytes) ----
#define SA      0            // 16KB (128 rows x 128B)
#define SB      16384        // 16KB
#define S_XN    32768        // 512B
#define S_CN    33280        // 512B
#define S_IV    33792        // 512B
#define S_STAGE 34304        // 8 warps x 1KB
#define SMEM_TOTAL 42496

__device__ __forceinline__ uint32_t s2u(const void* p) {
    uint32_t a;
    asm("{ .reg .u64 t; cvta.to.shared.u64 t, %1; cvt.u32.u64 %0, t; }" : "=r"(a) : "l"(p));
    return a;
}
__device__ __forceinline__ void cp16(uint32_t dst, const void* src) {
    asm volatile("cp.async.cg.shared.global [%0], [%1], 16;" :: "r"(dst), "l"(src));
}
__device__ __forceinline__ void ldm_x4(uint32_t* r, uint32_t addr) {
    asm volatile("ldmatrix.sync.aligned.m8n8.x4.shared.b16 {%0,%1,%2,%3}, [%4];"
                 : "=r"(r[0]), "=r"(r[1]), "=r"(r[2]), "=r"(r[3]) : "r"(addr));
}
__device__ __forceinline__ void stm_x4(uint32_t addr, uint32_t r0, uint32_t r1,
                                       uint32_t r2, uint32_t r3) {
    asm volatile("stmatrix.sync.aligned.m8n8.x4.shared.b16 [%0], {%1,%2,%3,%4};"
                 :: "r"(addr), "r"(r0), "r"(r1), "r"(r2), "r"(r3) : "memory");
}
__device__ __forceinline__ void mma_h(uint32_t* c, const uint32_t* a,
                                      uint32_t b0, uint32_t b1) {
    asm volatile(
        "mma.sync.aligned.m16n8k16.row.col.f16.f16.f16.f16 "
        "{%0,%1}, {%2,%3,%4,%5}, {%6,%7}, {%0,%1};"
        : "+r"(c[0]), "+r"(c[1])
        : "r"(a[0]), "r"(a[1]), "r"(a[2]), "r"(a[3]), "r"(b0), "r"(b1));
}
__device__ __forceinline__ float ex2a(float x) {
    float r;
    asm("ex2.approx.f32 %0, %1;" : "=f"(r) : "f"(x));
    return r;
}

// ---- prep (fused): f32 -> fp16, row norms, inv_sigma2 ----
__global__ void prep_all(const float* __restrict__ x, const float* __restrict__ c,
                         const float* __restrict__ ls) {
    int gw = (blockIdx.x * blockDim.x + threadIdx.x) >> 5;
    int lane = threadIdx.x & 31;
    const float* src;
    __half2* dst;
    int row;
    if (gw < B_ROWS) {
        row = gw; src = x; dst = (__half2*)g_xh;
    } else {
        row = gw - B_ROWS;
        if (row >= OUT_DIM) return;
        src = c; dst = (__half2*)g_ch;
    }
    float2 v = ((const float2*)src)[row * 32 + lane];
    dst[row * 32 + lane] = __floats2half2_rn(v.x, v.y);
    float s = v.x * v.x + v.y * v.y;
#pragma unroll
    for (int o = 16; o; o >>= 1) s += __shfl_xor_sync(0xffffffffu, s, o);
    if (lane == 0) {
        if (gw < B_ROWS) g_xn[row] = s;
        else { g_cn[row] = s; g_iv[row] = __expf(-2.0f * ls[row]); }
    }
}

// ---- main: 128x128 tile, 64x32 warp tiles, f16 acc, 3 CTA/SM ----
__global__ void __launch_bounds__(256, 3)
rbf_mma(float* __restrict__ out) {
    extern __shared__ char smem[];
    const uint32_t sb = s2u(smem);
    const int tid = threadIdx.x;
    const int bn = blockIdx.x * BN;
    const int bm = blockIdx.y * BM;

    // ---- global -> smem via cp.async, XOR-swizzled (q -> q ^ (row&7)) ----
    {
        const __half* ax = g_xh + (size_t)bm * IN_DIM;
        const __half* bc = g_ch + (size_t)bn * IN_DIM;
#pragma unroll
        for (int i = 0; i < 4; i++) {
            int l = tid + i * 256;
            int row = l >> 3, q = l & 7;
            uint32_t off = (uint32_t)(row * 128 + ((q ^ (row & 7)) << 4));
            cp16(sb + SA + off, ax + l * 8);
            cp16(sb + SB + off, bc + l * 8);
        }
        if (tid < 32)       cp16(sb + S_XN + tid * 16, g_xn + bm + tid * 4);
        else if (tid < 64)  cp16(sb + S_CN + (tid - 32) * 16, g_cn + bn + (tid - 32) * 4);
        else if (tid < 96)  cp16(sb + S_IV + (tid - 64) * 16, g_iv + bn + (tid - 64) * 4);
        asm volatile("cp.async.commit_group;" ::: "memory");
        asm volatile("cp.async.wait_group 0;" ::: "memory");
    }
    __syncthreads();

    const int wid = tid >> 5, lane = tid & 31;
    const int wm = wid >> 2, wn = wid & 3;   // 2x4 warp grid, 64x32 warp tiles
    const int lrow = lane & 15;
    const int ksel = lane >> 4;
    const int szk = lrow & 7;

    uint32_t aBase[4], bBase[2];
#pragma unroll
    for (int t = 0; t < 4; t++)
        aBase[t] = sb + SA + (wm * 64 + t * 16 + lrow) * 128;
#pragma unroll
    for (int t = 0; t < 2; t++)
        bBase[t] = sb + SB + (wn * 32 + t * 16 + lrow) * 128;

    uint32_t acc[4][4][2];                   // f16x2-packed accumulators
#pragma unroll
    for (int i = 0; i < 4; i++)
#pragma unroll
        for (int j = 0; j < 4; j++) { acc[i][j][0] = 0u; acc[i][j][1] = 0u; }

#pragma unroll
    for (int ks = 0; ks < 4; ks++) {
        const int kc = ks * 2 + ksel;
        const uint32_t ko = (uint32_t)((kc ^ szk) << 4);
        uint32_t Ah[4][4], Bh[2][4];
#pragma unroll
        for (int t = 0; t < 4; t++) ldm_x4(Ah[t], aBase[t] + ko);
#pragma unroll
        for (int t = 0; t < 2; t++) ldm_x4(Bh[t], bBase[t] + ko);
#pragma unroll
        for (int mt = 0; mt < 4; mt++)
#pragma unroll
            for (int p = 0; p < 2; p++) {
                mma_h(acc[mt][p * 2 + 0], Ah[mt], Bh[p][0], Bh[p][2]);
                mma_h(acc[mt][p * 2 + 1], Ah[mt], Bh[p][1], Bh[p][3]);
            }
    }

    // ---- epilogue: swizzled stage (rot = rr+2m), LDS.64 -> 1 STG.128/lane ----
    const float* xn_s = (const float*)(smem + S_XN);
    const float* cn_s = (const float*)(smem + S_CN);
    const float* iv_s = (const float*)(smem + S_IV);
    const float L2E = 1.4426950408889634f;

    const int q4 = lane & 7;             // 4-col chunk (0..7)
    const int rsub = lane >> 3;          // 0..3
    float s4[4], ivl4[4], nci4[4];
#pragma unroll
    for (int j = 0; j < 4; j++) {
        int col = wn * 32 + q4 * 4 + j;
        float ivl = iv_s[col] * L2E;
        ivl4[j] = ivl;
        s4[j] = 2.0f * ivl;
        nci4[j] = -cn_s[col] * ivl;
    }

    const uint32_t wstage = sb + S_STAGE + wid * 1024;
    const int mq_st = lane >> 3;         // stm matrix select (0..3)
    const int rr_st = lane & 7;
    const int mrd = q4 >> 1;             // readback matrix within group
    const int sub = q4 & 1;

#pragma unroll
    for (int mt = 0; mt < 4; mt++) {
#pragma unroll
        for (int g = 0; g < 2; g++) {
            int m = g * 4 + mq_st;
            uint32_t a = wstage + (uint32_t)(m * 128 + (((rr_st + 2 * m) & 7) << 4));
            stm_x4(a, acc[mt][0][g], acc[mt][1][g], acc[mt][2][g], acc[mt][3][g]);
        }
        __syncwarp();

#pragma unroll
        for (int k = 0; k < 4; k++) {
            int r = k * 4 + rsub;            // 0..15
            int g = r >> 3, rr = r & 7;
            int m = g * 4 + mrd;
            uint32_t a = wstage + (uint32_t)(m * 128 + (((rr + 2 * m) & 7) << 4) + sub * 8);
            uint2 raw = *(const uint2*)(smem + (a - sb));
            float2 f0 = __half22float2(*reinterpret_cast<__half2*>(&raw.x));
            float2 f1 = __half22float2(*reinterpret_cast<__half2*>(&raw.y));
            int row = wm * 64 + mt * 16 + r;
            float nxn = -xn_s[row];
            float4 o;
            o.x = ex2a(fmaf(f0.x, s4[0], fmaf(nxn, ivl4[0], nci4[0])));
            o.y = ex2a(fmaf(f0.y, s4[1], fmaf(nxn, ivl4[1], nci4[1])));
            o.z = ex2a(fmaf(f1.x, s4[2], fmaf(nxn, ivl4[2], nci4[2])));
            o.w = ex2a(fmaf(f1.y, s4[3], fmaf(nxn, ivl4[3], nci4[3])));
            *(float4*)(out + (size_t)(bm + row) * OUT_DIM + bn + wn * 32 + q4 * 4) = o;
        }
        __syncwarp();
    }
}

extern "C" void kernel_launch(void* const* d_in, const int* in_sizes, int n_in,
                              void* d_out, int out_size) {
    const float* x  = (const float*)d_in[0];
    const float* c  = (const float*)d_in[1];
    const float* ls = (const float*)d_in[2];
    float* out = (float*)d_out;
    (void)in_sizes; (void)n_in; (void)out_size;

    cudaFuncSetAttribute(rbf_mma, cudaFuncAttributeMaxDynamicSharedMemorySize, SMEM_TOTAL);

    prep_all<<<(B_ROWS + OUT_DIM) / 8, 256>>>(x, c, ls);

    dim3 grid(OUT_DIM / BN, B_ROWS / BM);
    rbf_mma<<<grid, 256, SMEM_TOTAL>>>(out);
}